// round 4
// baseline (speedup 1.0000x reference)
#include <cuda_runtime.h>

#define NN 50000
#define EE 800000
#define DD 128
#define BB 100
#define LSLOPE 0.01f
typedef unsigned long long u64;

#define FMA2(d,a,b,c) asm("fma.rn.f32x2 %0, %1, %2, %3;" : "=l"(d) : "l"(a), "l"(b), "l"(c))
#define PACK2(d,x)    asm("mov.b64 %0, {%1, %1};" : "=l"(d) : "r"(__float_as_uint(x)))
#define UNPK2(lo,hi,v) asm("mov.b64 {%0, %1}, %2;" : "=r"(lo), "=r"(hi) : "l"(v))

__device__ float d_aterm[NN*DD];
__device__ float d_bterm[NN*DD];
__device__ float d_c1[NN*DD];
__device__ float d_hfsum[NN*DD];
__device__ float d_npool[BB*DD];
__device__ float d_epool[BB*DD];
__device__ float d_gpool[BB*DD];
__device__ float d_gnew[BB*DD];
__device__ int   d_deg[NN];
__device__ int   d_nncnt[BB];
__device__ int   d_necnt[BB];

__device__ __forceinline__ float lrelu(float x){ return x > 0.f ? x : LSLOPE*x; }

__device__ __forceinline__ void red4(float* p, float4 v){
  asm volatile("red.global.add.v4.f32 [%0], {%1, %2, %3, %4};"
               :: "l"(p), "f"(v.x), "f"(v.y), "f"(v.z), "f"(v.w) : "memory");
}

__device__ __forceinline__ void unpack_acc(const u64* a, float* v){
  unsigned lo, hi;
  UNPK2(lo,hi,a[0]); v[0]=__uint_as_float(lo); v[1]=__uint_as_float(hi);
  UNPK2(lo,hi,a[1]); v[2]=__uint_as_float(lo); v[3]=__uint_as_float(hi);
  UNPK2(lo,hi,a[2]); v[4]=__uint_as_float(lo); v[5]=__uint_as_float(hi);
  UNPK2(lo,hi,a[3]); v[6]=__uint_as_float(lo); v[7]=__uint_as_float(hi);
}

#define ZACC8(acc) { _Pragma("unroll") for (int zi=0; zi<8; ++zi){ _Pragma("unroll") for (int zj=0; zj<4; ++zj) acc[zi][zj]=0ull; } }
#define ZACC4(acc) { _Pragma("unroll") for (int zi=0; zi<4; ++zi){ _Pragma("unroll") for (int zj=0; zj<4; ++zj) acc[zi][zj]=0ull; } }

// ---- high-intensity GEMM: acc(8x8 per thread) += Xs(128x128 smem) @ W(128x128 gmem) ----
// 256 threads: ty=tid>>4 -> rows ty*8..+7, tx=tid&15 -> cols tx*8..+7
__device__ __forceinline__ void gemm128(const float* Xs, const float* __restrict__ W,
                                        u64 acc[8][4], float* Bs, int ty, int tx, int tid)
{
  int r0 = ty*8;
  #pragma unroll 1
  for (int k0 = 0; k0 < 128; k0 += 16) {
    __syncthreads();
    { int kr = tid >> 4, cc = (tid & 15) * 8;
      const float4* s4 = reinterpret_cast<const float4*>(W + (k0 + kr)*DD + cc);
      float4* t4 = reinterpret_cast<float4*>(Bs + kr*DD + cc);
      t4[0] = s4[0]; t4[1] = s4[1];
    }
    __syncthreads();
    #pragma unroll
    for (int kk = 0; kk < 16; kk += 4) {
      float4 a[8];
      #pragma unroll
      for (int r = 0; r < 8; ++r)
        a[r] = *reinterpret_cast<const float4*>(Xs + (r0+r)*DD + k0 + kk);
      #pragma unroll
      for (int k4 = 0; k4 < 4; ++k4) {
        const float* br = Bs + (kk+k4)*DD + tx*8;
        u64 b0 = *reinterpret_cast<const u64*>(br);
        u64 b1 = *reinterpret_cast<const u64*>(br+2);
        u64 b2 = *reinterpret_cast<const u64*>(br+4);
        u64 b3 = *reinterpret_cast<const u64*>(br+6);
        #pragma unroll
        for (int r = 0; r < 8; ++r) {
          float av = (k4==0) ? a[r].x : (k4==1) ? a[r].y : (k4==2) ? a[r].z : a[r].w;
          u64 aa; PACK2(aa, av);
          FMA2(acc[r][0], aa, b0, acc[r][0]);
          FMA2(acc[r][1], aa, b1, acc[r][1]);
          FMA2(acc[r][2], aa, b2, acc[r][2]);
          FMA2(acc[r][3], aa, b3, acc[r][3]);
        }
      }
    }
  }
}

// ---- legacy 64-row GEMM used by kC: acc(4x8) += As(64x128 smem) @ W ----
__device__ __forceinline__ void mm_pass(const float* As, const float* __restrict__ W,
                                        u64 acc[4][4], float* Bs, int ty, int tx, int tid)
{
  #pragma unroll 1
  for (int k0 = 0; k0 < 128; k0 += 16) {
    __syncthreads();
    { int kr = tid >> 4, cc = (tid & 15) << 3;
      const float4* s4 = reinterpret_cast<const float4*>(W + (k0 + kr)*DD + cc);
      float4* t4 = reinterpret_cast<float4*>(Bs + kr*DD + cc);
      t4[0] = s4[0]; t4[1] = s4[1];
    }
    __syncthreads();
    #pragma unroll 4
    for (int k = 0; k < 16; ++k) {
      const float* br = Bs + k*DD;
      u64 b0 = *reinterpret_cast<const u64*>(br + tx*4);
      u64 b1 = *reinterpret_cast<const u64*>(br + tx*4 + 2);
      u64 b2 = *reinterpret_cast<const u64*>(br + 64 + tx*4);
      u64 b3 = *reinterpret_cast<const u64*>(br + 64 + tx*4 + 2);
      #pragma unroll
      for (int i = 0; i < 4; ++i) {
        u64 aa; PACK2(aa, As[(ty*4 + i)*DD + k0 + k]);
        FMA2(acc[i][0], aa, b0, acc[i][0]);
        FMA2(acc[i][1], aa, b1, acc[i][1]);
        FMA2(acc[i][2], aa, b2, acc[i][2]);
        FMA2(acc[i][3], aa, b3, acc[i][3]);
      }
    }
  }
}

__global__ void kInit(){
  int idx = blockIdx.x*blockDim.x + threadIdx.x;
  if (idx < NN*DD) d_hfsum[idx] = 0.f;
  if (idx < BB*DD) { d_npool[idx]=0.f; d_epool[idx]=0.f; d_gpool[idx]=0.f; }
  if (idx < NN) d_deg[idx] = 0;
  if (idx < BB) { d_nncnt[idx]=0; d_necnt[idx]=0; }
}

__global__ void kCounts(const int* __restrict__ dst, const int* __restrict__ n2g){
  int idx = blockIdx.x*blockDim.x + threadIdx.x;
  if (idx < EE) atomicAdd(&d_deg[dst[idx]], 1);
  if (idx < NN) atomicAdd(&d_nncnt[n2g[idx]], 1);
}

// ---- kA: per-node precompute (128-row tiles, 8x8 regs) ----
__global__ __launch_bounds__(256) void kA(
    const float* __restrict__ node, const float* __restrict__ graph,
    const float* __restrict__ Wn, const float* __restrict__ bn,
    const float* __restrict__ Wg, const float* __restrict__ bg,
    const float* __restrict__ Weu, const float* __restrict__ beu,
    const float* __restrict__ Wnu, const float* __restrict__ bnu)
{
  extern __shared__ float sm[];
  float* Xs = sm;              // node -> h
  float* Ys = sm + 128*DD;     // graph -> u
  float* Bs = sm + 2*128*DD;
  int tid = threadIdx.x, tx = tid & 15, ty = tid >> 4;
  int row0 = blockIdx.x * 128, r0 = ty*8, c0 = tx*8;

  for (int i = tid; i < 128*32; i += 256) {
    int n = row0 + (i >> 5), q = i & 31;
    float4 v = make_float4(0,0,0,0), g = v;
    if (n < NN) {
      v = reinterpret_cast<const float4*>(node)[(size_t)n*32 + q];
      g = reinterpret_cast<const float4*>(graph)[(size_t)n*32 + q];
    }
    reinterpret_cast<float4*>(Xs)[i] = v;
    reinterpret_cast<float4*>(Ys)[i] = g;
  }

  u64 acc[8][4];
  float4 w0, w1;

  // h = lrelu(node@Wn + bn) -> Xs
  ZACC8(acc); gemm128(Xs, Wn, acc, Bs, ty, tx, tid);
  __syncthreads();
  w0 = *reinterpret_cast<const float4*>(bn + c0); w1 = *reinterpret_cast<const float4*>(bn + c0 + 4);
  #pragma unroll
  for (int r=0;r<8;r++){
    float v[8]; unpack_acc(acc[r], v);
    *reinterpret_cast<float4*>(Xs + (r0+r)*DD + c0) =
      make_float4(lrelu(v[0]+w0.x), lrelu(v[1]+w0.y), lrelu(v[2]+w0.z), lrelu(v[3]+w0.w));
    *reinterpret_cast<float4*>(Xs + (r0+r)*DD + c0 + 4) =
      make_float4(lrelu(v[4]+w1.x), lrelu(v[5]+w1.y), lrelu(v[6]+w1.z), lrelu(v[7]+w1.w));
  }

  // u = lrelu(graph@Wg + bg) -> Ys
  ZACC8(acc); gemm128(Ys, Wg, acc, Bs, ty, tx, tid);
  __syncthreads();
  w0 = *reinterpret_cast<const float4*>(bg + c0); w1 = *reinterpret_cast<const float4*>(bg + c0 + 4);
  #pragma unroll
  for (int r=0;r<8;r++){
    float v[8]; unpack_acc(acc[r], v);
    *reinterpret_cast<float4*>(Ys + (r0+r)*DD + c0) =
      make_float4(lrelu(v[0]+w0.x), lrelu(v[1]+w0.y), lrelu(v[2]+w0.z), lrelu(v[3]+w0.w));
    *reinterpret_cast<float4*>(Ys + (r0+r)*DD + c0 + 4) =
      make_float4(lrelu(v[4]+w1.x), lrelu(v[5]+w1.y), lrelu(v[6]+w1.z), lrelu(v[7]+w1.w));
  }

  // aterm = h@Weu1
  ZACC8(acc); gemm128(Xs, Weu, acc, Bs, ty, tx, tid);
  #pragma unroll
  for (int r=0;r<8;r++){
    int n = row0 + r0 + r; if (n >= NN) continue;
    float v[8]; unpack_acc(acc[r], v);
    *reinterpret_cast<float4*>(d_aterm + (size_t)n*DD + c0)     = make_float4(v[0],v[1],v[2],v[3]);
    *reinterpret_cast<float4*>(d_aterm + (size_t)n*DD + c0 + 4) = make_float4(v[4],v[5],v[6],v[7]);
  }

  // bterm = h@Weu2 + u@Weu4 + beu
  ZACC8(acc); gemm128(Xs, Weu + 128*DD, acc, Bs, ty, tx, tid);
  gemm128(Ys, Weu + 384*DD, acc, Bs, ty, tx, tid);
  w0 = *reinterpret_cast<const float4*>(beu + c0); w1 = *reinterpret_cast<const float4*>(beu + c0 + 4);
  #pragma unroll
  for (int r=0;r<8;r++){
    int n = row0 + r0 + r; if (n >= NN) continue;
    float v[8]; unpack_acc(acc[r], v);
    *reinterpret_cast<float4*>(d_bterm + (size_t)n*DD + c0) =
      make_float4(v[0]+w0.x, v[1]+w0.y, v[2]+w0.z, v[3]+w0.w);
    *reinterpret_cast<float4*>(d_bterm + (size_t)n*DD + c0 + 4) =
      make_float4(v[4]+w1.x, v[5]+w1.y, v[6]+w1.z, v[7]+w1.w);
  }

  // c1 = h@Wnu1 + u@Wnu3 + bnu
  ZACC8(acc); gemm128(Xs, Wnu, acc, Bs, ty, tx, tid);
  gemm128(Ys, Wnu + 256*DD, acc, Bs, ty, tx, tid);
  w0 = *reinterpret_cast<const float4*>(bnu + c0); w1 = *reinterpret_cast<const float4*>(bnu + c0 + 4);
  #pragma unroll
  for (int r=0;r<8;r++){
    int n = row0 + r0 + r; if (n >= NN) continue;
    float v[8]; unpack_acc(acc[r], v);
    *reinterpret_cast<float4*>(d_c1 + (size_t)n*DD + c0) =
      make_float4(v[0]+w0.x, v[1]+w0.y, v[2]+w0.z, v[3]+w0.w);
    *reinterpret_cast<float4*>(d_c1 + (size_t)n*DD + c0 + 4) =
      make_float4(v[4]+w1.x, v[5]+w1.y, v[6]+w1.z, v[7]+w1.w);
  }
}

// ---- kB: edge kernel (128-edge tiles, 8x8 regs, Xs reused edge->f) ----
__global__ __launch_bounds__(256) void kB(
    const float* __restrict__ edge, const int* __restrict__ src, const int* __restrict__ dst,
    const float* __restrict__ We, const float* __restrict__ be,
    const float* __restrict__ Weu, float* __restrict__ out_edge)
{
  extern __shared__ float sm[];
  float* Xs = sm;            // edge feats, then f
  float* Bs = sm + 128*DD;
  int tid = threadIdx.x, tx = tid & 15, ty = tid >> 4;
  long row0 = (long)blockIdx.x * 128;
  int r0 = ty*8, c0 = tx*8;

  for (int i = tid; i < 128*32; i += 256)
    reinterpret_cast<float4*>(Xs)[i] = reinterpret_cast<const float4*>(edge)[row0*32 + i];

  u64 acc[8][4];
  ZACC8(acc); gemm128(Xs, We, acc, Bs, ty, tx, tid);
  __syncthreads();   // all Xs reads done before overwrite with f
  {
    float4 w0 = *reinterpret_cast<const float4*>(be + c0);
    float4 w1 = *reinterpret_cast<const float4*>(be + c0 + 4);
    #pragma unroll
    for (int r=0;r<8;r++){
      float v[8]; unpack_acc(acc[r], v);
      *reinterpret_cast<float4*>(Xs + (r0+r)*DD + c0) =
        make_float4(lrelu(v[0]+w0.x), lrelu(v[1]+w0.y), lrelu(v[2]+w0.z), lrelu(v[3]+w0.w));
      *reinterpret_cast<float4*>(Xs + (r0+r)*DD + c0 + 4) =
        make_float4(lrelu(v[4]+w1.x), lrelu(v[5]+w1.y), lrelu(v[6]+w1.z), lrelu(v[7]+w1.w));
    }
  }
  ZACC8(acc); gemm128(Xs, Weu + 256*DD, acc, Bs, ty, tx, tid);

  #pragma unroll
  for (int r=0;r<8;r++){
    long e = row0 + r0 + r;
    int s = src[e], d = dst[e];
    float v[8]; unpack_acc(acc[r], v);
    float4 a0 = *reinterpret_cast<const float4*>(d_aterm + (size_t)s*DD + c0);
    float4 a1 = *reinterpret_cast<const float4*>(d_aterm + (size_t)s*DD + c0 + 4);
    float4 b0 = *reinterpret_cast<const float4*>(d_bterm + (size_t)d*DD + c0);
    float4 b1 = *reinterpret_cast<const float4*>(d_bterm + (size_t)d*DD + c0 + 4);
    float f0=lrelu(v[0]+a0.x+b0.x), f1=lrelu(v[1]+a0.y+b0.y);
    float f2=lrelu(v[2]+a0.z+b0.z), f3=lrelu(v[3]+a0.w+b0.w);
    float f4=lrelu(v[4]+a1.x+b1.x), f5=lrelu(v[5]+a1.y+b1.y);
    float f6=lrelu(v[6]+a1.z+b1.z), f7=lrelu(v[7]+a1.w+b1.w);
    float4 e0 = reinterpret_cast<const float4*>(edge)[e*32 + tx*2];
    float4 e1 = reinterpret_cast<const float4*>(edge)[e*32 + tx*2 + 1];
    *reinterpret_cast<float4*>(out_edge + (size_t)e*DD + c0) =
      make_float4(f0+e0.x, f1+e0.y, f2+e0.z, f3+e0.w);
    *reinterpret_cast<float4*>(out_edge + (size_t)e*DD + c0 + 4) =
      make_float4(f4+e1.x, f5+e1.y, f6+e1.z, f7+e1.w);
    red4(d_hfsum + (size_t)d*DD + c0,     make_float4(f0,f1,f2,f3));
    red4(d_hfsum + (size_t)d*DD + c0 + 4, make_float4(f4,f5,f6,f7));
  }
}

// ---- kC: node update + pooling (unchanged 64-row layout) ----
__global__ __launch_bounds__(256) void kC(
    const float* __restrict__ node, const float* __restrict__ graph,
    const int* __restrict__ n2g, const float* __restrict__ Wnu,
    float* __restrict__ out_node)
{
  extern __shared__ float sm[];
  float* Hf = sm; float* Bs = sm + 64*DD;
  int*   sG = reinterpret_cast<int*>(sm + 80*DD);
  float* sD = sm + 80*DD + 64;
  int tid = threadIdx.x, tx = tid & 15, ty = tid >> 4;
  int row0 = blockIdx.x * 64, c0 = tx*4, cB = 64 + tx*4;

  for (int i = tid; i < 64*32; i += 256) {
    int n = row0 + (i >> 5), q = i & 31;
    float4 v = make_float4(0,0,0,0);
    if (n < NN) v = reinterpret_cast<const float4*>(d_hfsum)[(size_t)n*32 + q];
    reinterpret_cast<float4*>(Hf)[i] = v;
  }
  if (tid < 64) {
    int n = row0 + tid, g = 0, dg = 0;
    if (n < NN) { g = n2g[n]; dg = d_deg[n]; atomicAdd(&d_necnt[g], dg); }
    sG[tid] = g;
    sD[tid] = 1.f / fmaxf((float)dg, 1.f);
  }
  __syncthreads();

  #pragma unroll
  for (int i=0;i<4;i++){
    int r = ty*4+i, n = row0 + r; if (n >= NN) continue;
    int g = sG[r];
    float4 h0 = reinterpret_cast<float4*>(Hf)[r*32 + tx];
    float4 h1 = reinterpret_cast<float4*>(Hf)[r*32 + 16 + tx];
    red4(d_epool + g*DD + c0, h0);
    red4(d_epool + g*DD + cB, h1);
    float4 g0 = reinterpret_cast<const float4*>(graph)[(size_t)n*32 + tx];
    float4 g1 = reinterpret_cast<const float4*>(graph)[(size_t)n*32 + 16 + tx];
    red4(d_gpool + g*DD + c0, g0);
    red4(d_gpool + g*DD + cB, g1);
    float rd = sD[r];
    h0.x*=rd; h0.y*=rd; h0.z*=rd; h0.w*=rd;
    h1.x*=rd; h1.y*=rd; h1.z*=rd; h1.w*=rd;
    reinterpret_cast<float4*>(Hf)[r*32 + tx] = h0;
    reinterpret_cast<float4*>(Hf)[r*32 + 16 + tx] = h1;
  }

  u64 acc[4][4];
  ZACC4(acc); mm_pass(Hf, Wnu + 128*DD, acc, Bs, ty, tx, tid);

  #pragma unroll
  for (int i=0;i<4;i++){
    int r = ty*4+i, n = row0 + r; if (n >= NN) continue;
    float v[8]; unpack_acc(acc[i], v);
    const float* cr = d_c1 + (size_t)n*DD;
    float f0=lrelu(v[0]+cr[c0]),   f1=lrelu(v[1]+cr[c0+1]);
    float f2=lrelu(v[2]+cr[c0+2]), f3=lrelu(v[3]+cr[c0+3]);
    float f4=lrelu(v[4]+cr[cB]),   f5=lrelu(v[5]+cr[cB+1]);
    float f6=lrelu(v[6]+cr[cB+2]), f7=lrelu(v[7]+cr[cB+3]);
    float4 n0 = reinterpret_cast<const float4*>(node)[(size_t)n*32 + tx];
    float4 n1 = reinterpret_cast<const float4*>(node)[(size_t)n*32 + 16 + tx];
    *reinterpret_cast<float4*>(out_node + (size_t)n*DD + c0) = make_float4(f0+n0.x,f1+n0.y,f2+n0.z,f3+n0.w);
    *reinterpret_cast<float4*>(out_node + (size_t)n*DD + cB) = make_float4(f4+n1.x,f5+n1.y,f6+n1.z,f7+n1.w);
    int g = sG[r];
    red4(d_npool + g*DD + c0, make_float4(f0,f1,f2,f3));
    red4(d_npool + g*DD + cB, make_float4(f4,f5,f6,f7));
  }
}

__global__ void kD(const float* __restrict__ Wnu, const float* __restrict__ bnu){
  __shared__ float sp[3*DD];
  int g = blockIdx.x, j = threadIdx.x;
  float rn = 1.f / fmaxf((float)d_nncnt[g], 1.f);
  float re = 1.f / fmaxf((float)d_necnt[g], 1.f);
  sp[j]      = d_npool[g*DD+j]*rn;
  sp[DD+j]   = d_epool[g*DD+j]*re;
  sp[2*DD+j] = d_gpool[g*DD+j]*rn;
  __syncthreads();
  float a = bnu[j];
  #pragma unroll 4
  for (int k = 0; k < 3*DD; ++k) a = fmaf(sp[k], Wnu[k*DD+j], a);
  d_gnew[g*DD+j] = lrelu(a);
}

__global__ void kE(const float* __restrict__ graph, const int* __restrict__ n2g,
                   float* __restrict__ out_graph){
  int t = blockIdx.x*blockDim.x + threadIdx.x;
  if (t >= NN*32) return;
  int n = t >> 5, q = t & 31;
  int g = n2g[n];
  float4 gv = reinterpret_cast<const float4*>(d_gnew)[g*32 + q];
  float4 rv = reinterpret_cast<const float4*>(graph)[(size_t)n*32 + q];
  reinterpret_cast<float4*>(out_graph)[t] = make_float4(gv.x+rv.x, gv.y+rv.y, gv.z+rv.z, gv.w+rv.w);
}

extern "C" void kernel_launch(void* const* d_in, const int* in_sizes, int n_in,
                              void* d_out, int out_size) {
  const float* node  = (const float*)d_in[0];
  const float* edge  = (const float*)d_in[1];
  const float* graph = (const float*)d_in[2];
  const int*   src   = (const int*)d_in[3];
  const int*   dst   = (const int*)d_in[4];
  const int*   n2g   = (const int*)d_in[5];
  const float* Wn  = (const float*)d_in[6];
  const float* bn  = (const float*)d_in[7];
  const float* We  = (const float*)d_in[8];
  const float* be  = (const float*)d_in[9];
  const float* Wg  = (const float*)d_in[10];
  const float* bg  = (const float*)d_in[11];
  const float* Weu = (const float*)d_in[12];
  const float* beu = (const float*)d_in[13];
  const float* Wnu = (const float*)d_in[14];
  const float* bnu = (const float*)d_in[15];
  float* out_node  = (float*)d_out;
  float* out_edge  = out_node + (size_t)NN*DD;
  float* out_graph = out_edge + (size_t)EE*DD;

  const int SMA = (2*128*DD + 16*DD) * 4;   // 139264 B
  const int SMB = (128*DD + 16*DD) * 4;     // 73728 B
  const int SMC = (80*DD) * 4 + 64*4 + 64*4;
  cudaFuncSetAttribute(kA, cudaFuncAttributeMaxDynamicSharedMemorySize, SMA);
  cudaFuncSetAttribute(kB, cudaFuncAttributeMaxDynamicSharedMemorySize, SMB);
  cudaFuncSetAttribute(kC, cudaFuncAttributeMaxDynamicSharedMemorySize, SMC);

  kInit<<<(NN*DD + 255)/256, 256>>>();
  kCounts<<<(EE + 255)/256, 256>>>(dst, n2g);
  kA<<<(NN + 127)/128, 256, SMA>>>(node, graph, Wn, bn, Wg, bg, Weu, beu, Wnu, bnu);
  kB<<<EE/128, 256, SMB>>>(edge, src, dst, We, be, Weu, out_edge);
  kC<<<(NN + 63)/64, 256, SMC>>>(node, graph, n2g, Wnu, out_node);
  kD<<<BB, DD>>>(Wnu, bnu);
  kE<<<(NN*32 + 255)/256, 256>>>(graph, n2g, out_graph);
}

// round 7
// speedup vs baseline: 1.3989x; 1.3989x over previous
#include <cuda_runtime.h>
#include <cuda_bf16.h>

#define NN 50000
#define EE 800000
#define DD 128
#define BB 100
#define LSLOPE 0.01f
typedef unsigned long long u64;
typedef unsigned int u32;
typedef unsigned short u16;

#define FMA2(d,a,b,c) asm("fma.rn.f32x2 %0, %1, %2, %3;" : "=l"(d) : "l"(a), "l"(b), "l"(c))
#define PACK2(d,x)    asm("mov.b64 %0, {%1, %1};" : "=l"(d) : "r"(__float_as_uint(x)))
#define UNPK2(lo,hi,v) asm("mov.b64 {%0, %1}, %2;" : "=r"(lo), "=r"(hi) : "l"(v))

#define LDSM4(r0,r1,r2,r3,a) \
  asm volatile("ldmatrix.sync.aligned.m8n8.x4.shared.b16 {%0,%1,%2,%3}, [%4];" \
    : "=r"(r0),"=r"(r1),"=r"(r2),"=r"(r3) : "r"(a))

#define MMA16816(c, a0,a1,a2,a3, b0,b1) \
  asm volatile("mma.sync.aligned.m16n8k16.row.col.f32.bf16.bf16.f32 " \
    "{%0,%1,%2,%3}, {%4,%5,%6,%7}, {%8,%9}, {%0,%1,%2,%3};" \
    : "+f"((c)[0]),"+f"((c)[1]),"+f"((c)[2]),"+f"((c)[3]) \
    : "r"(a0),"r"(a1),"r"(a2),"r"(a3), "r"(b0),"r"(b1))

// ---------------- scratch ----------------
__device__ float d_aterm[NN*DD];
__device__ float d_bterm[NN*DD];
__device__ float d_c1[NN*DD];
__device__ float d_hfsum[NN*DD];
__device__ float d_npool[BB*DD];
__device__ float d_epool[BB*DD];
__device__ float d_gpool[BB*DD];
__device__ float d_gnew[BB*DD];
__device__ int   d_deg[NN];
__device__ int   d_nncnt[BB];
__device__ int   d_necnt[BB];
// transposed + bf16-split weights, padded stride 136 (272B rows)
#define WST 136
__device__ __align__(16) u16 d_wbh1[DD*WST], d_wbl1[DD*WST];   // We^T
__device__ __align__(16) u16 d_wbh2[DD*WST], d_wbl2[DD*WST];   // Weu3^T

__device__ __forceinline__ float lrelu(float x){ return x > 0.f ? x : LSLOPE*x; }

__device__ __forceinline__ void red4(float* p, float4 v){
  asm volatile("red.global.add.v4.f32 [%0], {%1, %2, %3, %4};"
               :: "l"(p), "f"(v.x), "f"(v.y), "f"(v.z), "f"(v.w) : "memory");
}
__device__ __forceinline__ void red2(float* p, float x, float y){
  asm volatile("red.global.add.v2.f32 [%0], {%1, %2};"
               :: "l"(p), "f"(x), "f"(y) : "memory");
}

__device__ __forceinline__ u32 smaddr(const void* p){
  u32 a; asm("{ .reg .u64 t; cvta.to.shared.u64 t, %1; cvt.u32.u64 %0, t; }" : "=r"(a) : "l"(p));
  return a;
}

__device__ __forceinline__ void unpack_acc(const u64* a, float* v){
  unsigned lo, hi;
  UNPK2(lo,hi,a[0]); v[0]=__uint_as_float(lo); v[1]=__uint_as_float(hi);
  UNPK2(lo,hi,a[1]); v[2]=__uint_as_float(lo); v[3]=__uint_as_float(hi);
  UNPK2(lo,hi,a[2]); v[4]=__uint_as_float(lo); v[5]=__uint_as_float(hi);
  UNPK2(lo,hi,a[3]); v[6]=__uint_as_float(lo); v[7]=__uint_as_float(hi);
}
#define ZACC4(acc) { _Pragma("unroll") for (int zi=0; zi<4; ++zi){ _Pragma("unroll") for (int zj=0; zj<4; ++zj) acc[zi][zj]=0ull; } }

// SIMT 64-row GEMM (kA/kC)
__device__ __forceinline__ void mm_pass(const float* As, const float* __restrict__ W,
                                        u64 acc[4][4], float* Bs, int ty, int tx, int tid)
{
  #pragma unroll 1
  for (int k0 = 0; k0 < 128; k0 += 16) {
    __syncthreads();
    { int kr = tid >> 4, cc = (tid & 15) << 3;
      const float4* s4 = reinterpret_cast<const float4*>(W + (k0 + kr)*DD + cc);
      float4* t4 = reinterpret_cast<float4*>(Bs + kr*DD + cc);
      t4[0] = s4[0]; t4[1] = s4[1];
    }
    __syncthreads();
    #pragma unroll 4
    for (int k = 0; k < 16; ++k) {
      const float* br = Bs + k*DD;
      u64 b0 = *reinterpret_cast<const u64*>(br + tx*4);
      u64 b1 = *reinterpret_cast<const u64*>(br + tx*4 + 2);
      u64 b2 = *reinterpret_cast<const u64*>(br + 64 + tx*4);
      u64 b3 = *reinterpret_cast<const u64*>(br + 64 + tx*4 + 2);
      #pragma unroll
      for (int i = 0; i < 4; ++i) {
        u64 aa; PACK2(aa, As[(ty*4 + i)*DD + k0 + k]);
        FMA2(acc[i][0], aa, b0, acc[i][0]);
        FMA2(acc[i][1], aa, b1, acc[i][1]);
        FMA2(acc[i][2], aa, b2, acc[i][2]);
        FMA2(acc[i][3], aa, b3, acc[i][3]);
      }
    }
  }
}

__global__ void kInit(){
  int idx = blockIdx.x*blockDim.x + threadIdx.x;
  if (idx < NN*DD) d_hfsum[idx] = 0.f;
  if (idx < BB*DD) { d_npool[idx]=0.f; d_epool[idx]=0.f; d_gpool[idx]=0.f; }
  if (idx < NN) d_deg[idx] = 0;
  if (idx < BB) { d_nncnt[idx]=0; d_necnt[idx]=0; }
}

__global__ void kCounts(const int* __restrict__ dst, const int* __restrict__ n2g){
  int idx = blockIdx.x*blockDim.x + threadIdx.x;
  if (idx < EE) atomicAdd(&d_deg[dst[idx]], 1);
  if (idx < NN) atomicAdd(&d_nncnt[n2g[idx]], 1);
}

// Weight prep: transpose + bf16 split into padded [n][k] layout.
__global__ void kW(const float* __restrict__ We, const float* __restrict__ Weu){
  int k = blockIdx.x, widx = blockIdx.y, n = threadIdx.x;
  const float* W = widx ? (Weu + 256*DD) : We;
  float w = W[k*DD + n];
  __nv_bfloat16 hi = __float2bfloat16(w);
  __nv_bfloat16 lo = __float2bfloat16(w - __bfloat162float(hi));
  int off = n*WST + k;
  if (widx) { d_wbh2[off] = __bfloat16_as_ushort(hi); d_wbl2[off] = __bfloat16_as_ushort(lo); }
  else      { d_wbh1[off] = __bfloat16_as_ushort(hi); d_wbl1[off] = __bfloat16_as_ushort(lo); }
}

// ---- kA: per-node precompute (SIMT) ----
__global__ __launch_bounds__(256) void kA(
    const float* __restrict__ node, const float* __restrict__ graph,
    const float* __restrict__ Wn, const float* __restrict__ bn,
    const float* __restrict__ Wg, const float* __restrict__ bg,
    const float* __restrict__ Weu, const float* __restrict__ beu,
    const float* __restrict__ Wnu, const float* __restrict__ bnu)
{
  extern __shared__ float sm[];
  float* Hs = sm; float* Us = sm + 64*DD; float* Bs = sm + 2*64*DD;
  int tid = threadIdx.x, tx = tid & 15, ty = tid >> 4;
  int row0 = blockIdx.x * 64, c0 = tx*4, cB = 64 + tx*4;

  for (int i = tid; i < 64*32; i += 256) {
    int n = row0 + (i >> 5), q = i & 31;
    float4 v = make_float4(0,0,0,0), g = v;
    if (n < NN) {
      v = reinterpret_cast<const float4*>(node)[(size_t)n*32 + q];
      g = reinterpret_cast<const float4*>(graph)[(size_t)n*32 + q];
    }
    reinterpret_cast<float4*>(Hs)[i] = v;
    reinterpret_cast<float4*>(Us)[i] = g;
  }

  u64 acc[4][4];
  ZACC4(acc); mm_pass(Hs, Wn, acc, Bs, ty, tx, tid);
  __syncthreads();
  #pragma unroll
  for (int i=0;i<4;i++){
    float v[8]; unpack_acc(acc[i], v);
    float* hr = Hs + (ty*4+i)*DD;
    hr[c0]=lrelu(v[0]+bn[c0]); hr[c0+1]=lrelu(v[1]+bn[c0+1]);
    hr[c0+2]=lrelu(v[2]+bn[c0+2]); hr[c0+3]=lrelu(v[3]+bn[c0+3]);
    hr[cB]=lrelu(v[4]+bn[cB]); hr[cB+1]=lrelu(v[5]+bn[cB+1]);
    hr[cB+2]=lrelu(v[6]+bn[cB+2]); hr[cB+3]=lrelu(v[7]+bn[cB+3]);
  }
  ZACC4(acc); mm_pass(Us, Wg, acc, Bs, ty, tx, tid);
  __syncthreads();
  #pragma unroll
  for (int i=0;i<4;i++){
    float v[8]; unpack_acc(acc[i], v);
    float* ur = Us + (ty*4+i)*DD;
    ur[c0]=lrelu(v[0]+bg[c0]); ur[c0+1]=lrelu(v[1]+bg[c0+1]);
    ur[c0+2]=lrelu(v[2]+bg[c0+2]); ur[c0+3]=lrelu(v[3]+bg[c0+3]);
    ur[cB]=lrelu(v[4]+bg[cB]); ur[cB+1]=lrelu(v[5]+bg[cB+1]);
    ur[cB+2]=lrelu(v[6]+bg[cB+2]); ur[cB+3]=lrelu(v[7]+bg[cB+3]);
  }

  ZACC4(acc); mm_pass(Hs, Weu, acc, Bs, ty, tx, tid);
  #pragma unroll
  for (int i=0;i<4;i++){
    int n = row0 + ty*4 + i; if (n >= NN) continue;
    float v[8]; unpack_acc(acc[i], v);
    *reinterpret_cast<float4*>(d_aterm + (size_t)n*DD + c0) = make_float4(v[0],v[1],v[2],v[3]);
    *reinterpret_cast<float4*>(d_aterm + (size_t)n*DD + cB) = make_float4(v[4],v[5],v[6],v[7]);
  }

  ZACC4(acc); mm_pass(Hs, Weu + 128*DD, acc, Bs, ty, tx, tid);
  mm_pass(Us, Weu + 384*DD, acc, Bs, ty, tx, tid);
  #pragma unroll
  for (int i=0;i<4;i++){
    int n = row0 + ty*4 + i; if (n >= NN) continue;
    float v[8]; unpack_acc(acc[i], v);
    *reinterpret_cast<float4*>(d_bterm + (size_t)n*DD + c0) =
      make_float4(v[0]+beu[c0], v[1]+beu[c0+1], v[2]+beu[c0+2], v[3]+beu[c0+3]);
    *reinterpret_cast<float4*>(d_bterm + (size_t)n*DD + cB) =
      make_float4(v[4]+beu[cB], v[5]+beu[cB+1], v[6]+beu[cB+2], v[7]+beu[cB+3]);
  }

  ZACC4(acc); mm_pass(Hs, Wnu, acc, Bs, ty, tx, tid);
  mm_pass(Us, Wnu + 256*DD, acc, Bs, ty, tx, tid);
  #pragma unroll
  for (int i=0;i<4;i++){
    int n = row0 + ty*4 + i; if (n >= NN) continue;
    float v[8]; unpack_acc(acc[i], v);
    *reinterpret_cast<float4*>(d_c1 + (size_t)n*DD + c0) =
      make_float4(v[0]+bnu[c0], v[1]+bnu[c0+1], v[2]+bnu[c0+2], v[3]+bnu[c0+3]);
    *reinterpret_cast<float4*>(d_c1 + (size_t)n*DD + cB) =
      make_float4(v[4]+bnu[cB], v[5]+bnu[cB+1], v[6]+bnu[cB+2], v[7]+bnu[cB+3]);
  }
}

// ---- kB: HMMA edge kernel ----
// smem bytes: Ah | Al | Bh | Bl (each 128*272=34816) | be(512) | src(512) | dst(512)
#define TB   34816
#define SM_AH 0
#define SM_AL TB
#define SM_BH (2*TB)
#define SM_BL (3*TB)
#define SM_BE (4*TB)
#define SM_SRC (4*TB + 512)
#define SM_DST (4*TB + 1024)
#define SM_TOT (4*TB + 1536)

// acc += A(smem tile, bf16 padded) @ B(smem tile)^T over K=128
__device__ __forceinline__ void hpass(u32 aBase, u32 bBase, float acc[2][8][4],
                                      int mbase, int nbase, int lane)
{
  int at = lane >> 3;
  int arow = (at & 1)*8 + (lane & 7);
  int acol = (at >> 1)*8;
  int bg = lane >> 3;
  int bn = (bg >> 1)*8 + (lane & 7);
  int bk = (bg & 1)*8;
  #pragma unroll
  for (int ks = 0; ks < 8; ++ks) {
    int k0 = ks*16;
    u32 af[2][4];
    #pragma unroll
    for (int mt = 0; mt < 2; ++mt) {
      u32 ad = aBase + (u32)(mbase + mt*16 + arow)*272 + (u32)(k0 + acol)*2;
      LDSM4(af[mt][0],af[mt][1],af[mt][2],af[mt][3], ad);
    }
    u32 bf[8][2];
    #pragma unroll
    for (int g = 0; g < 4; ++g) {
      u32 bd = bBase + (u32)(nbase + g*16 + bn)*272 + (u32)(k0 + bk)*2;
      u32 r0,r1,r2,r3;
      LDSM4(r0,r1,r2,r3, bd);
      bf[g*2][0]=r0; bf[g*2][1]=r1; bf[g*2+1][0]=r2; bf[g*2+1][1]=r3;
    }
    #pragma unroll
    for (int mt = 0; mt < 2; ++mt)
      #pragma unroll
      for (int nt = 0; nt < 8; ++nt)
        MMA16816(acc[mt][nt], af[mt][0],af[mt][1],af[mt][2],af[mt][3], bf[nt][0],bf[nt][1]);
  }
}

__global__ __launch_bounds__(256, 1) void kB(
    const float* __restrict__ edge, const int* __restrict__ src, const int* __restrict__ dst,
    const float* __restrict__ be, float* __restrict__ out_edge)
{
  extern __shared__ __align__(16) char smx[];
  float* sBe = (float*)(smx + SM_BE);
  int* sSrc = (int*)(smx + SM_SRC);
  int* sDst = (int*)(smx + SM_DST);
  u32 sbase = smaddr(smx);

  int tid = threadIdx.x, lane = tid & 31, wid = tid >> 5;
  int mbase = (wid & 3) * 32, nbase = (wid >> 2) * 64;
  long row0 = (long)blockIdx.x * 128;

  if (tid < DD) sBe[tid] = be[tid];
  if (tid < 128) { sSrc[tid] = src[row0 + tid]; sDst[tid] = dst[row0 + tid]; }

  // B tiles <- We^T hi/lo (padded layout, straight copy)
  for (int i = tid; i < DD*WST/8; i += 256) {
    reinterpret_cast<uint4*>(smx + SM_BH)[i] = reinterpret_cast<const uint4*>(d_wbh1)[i];
    reinterpret_cast<uint4*>(smx + SM_BL)[i] = reinterpret_cast<const uint4*>(d_wbl1)[i];
  }
  // A tiles <- edge fp32 split hi/lo  (4 floats -> 8 bytes, offset q*8)
  #pragma unroll 4
  for (int it = 0; it < 16; ++it) {
    int i = tid + it*256;
    int r = i >> 5, q = i & 31;
    float4 v = reinterpret_cast<const float4*>(edge)[row0*32 + i];
    __nv_bfloat16 h0=__float2bfloat16(v.x), h1=__float2bfloat16(v.y),
                  h2=__float2bfloat16(v.z), h3=__float2bfloat16(v.w);
    __nv_bfloat16 l0=__float2bfloat16(v.x-__bfloat162float(h0)),
                  l1=__float2bfloat16(v.y-__bfloat162float(h1)),
                  l2=__float2bfloat16(v.z-__bfloat162float(h2)),
                  l3=__float2bfloat16(v.w-__bfloat162float(h3));
    u32 off = (u32)r*272 + (u32)q*8;
    *reinterpret_cast<uint2*>(smx + SM_AH + off) =
      make_uint2(((u32)__bfloat16_as_ushort(h1)<<16)|__bfloat16_as_ushort(h0),
                 ((u32)__bfloat16_as_ushort(h3)<<16)|__bfloat16_as_ushort(h2));
    *reinterpret_cast<uint2*>(smx + SM_AL + off) =
      make_uint2(((u32)__bfloat16_as_ushort(l1)<<16)|__bfloat16_as_ushort(l0),
                 ((u32)__bfloat16_as_ushort(l3)<<16)|__bfloat16_as_ushort(l2));
  }
  __syncthreads();

  float acc[2][8][4];
  #pragma unroll
  for (int a=0;a<2;a++) for (int b=0;b<8;b++) for (int c=0;c<4;c++) acc[a][b][c]=0.f;

  // GEMM1: edge @ We^T  (3-pass split)
  hpass(sbase + SM_AH, sbase + SM_BH, acc, mbase, nbase, lane);
  hpass(sbase + SM_AH, sbase + SM_BL, acc, mbase, nbase, lane);
  hpass(sbase + SM_AL, sbase + SM_BH, acc, mbase, nbase, lane);
  __syncthreads();

  // epilogue 1: f = lrelu(D + be) -> back into A tiles (hi/lo); reload B tiles (Weu3)
  int qrow = lane >> 2, qcol = lane & 3;
  #pragma unroll
  for (int mt = 0; mt < 2; ++mt) {
    #pragma unroll
    for (int hr = 0; hr < 2; ++hr) {
      int row = mbase + mt*16 + qrow + hr*8;
      #pragma unroll
      for (int nt = 0; nt < 8; ++nt) {
        int c = nbase + nt*8 + qcol*2;
        float f0 = lrelu(acc[mt][nt][hr*2]   + sBe[c]);
        float f1 = lrelu(acc[mt][nt][hr*2+1] + sBe[c+1]);
        __nv_bfloat16 h0=__float2bfloat16(f0), h1=__float2bfloat16(f1);
        __nv_bfloat16 l0=__float2bfloat16(f0-__bfloat162float(h0)),
                      l1=__float2bfloat16(f1-__bfloat162float(h1));
        u32 off = (u32)row*272 + (u32)c*2;
        *reinterpret_cast<u32*>(smx + SM_AH + off) = ((u32)__bfloat16_as_ushort(h1)<<16)|__bfloat16_as_ushort(h0);
        *reinterpret_cast<u32*>(smx + SM_AL + off) = ((u32)__bfloat16_as_ushort(l1)<<16)|__bfloat16_as_ushort(l0);
      }
    }
  }
  for (int i = tid; i < DD*WST/8; i += 256) {
    reinterpret_cast<uint4*>(smx + SM_BH)[i] = reinterpret_cast<const uint4*>(d_wbh2)[i];
    reinterpret_cast<uint4*>(smx + SM_BL)[i] = reinterpret_cast<const uint4*>(d_wbl2)[i];
  }
  __syncthreads();

  #pragma unroll
  for (int a=0;a<2;a++) for (int b=0;b<8;b++) for (int c=0;c<4;c++) acc[a][b][c]=0.f;

  // GEMM2: f @ Weu3^T
  hpass(sbase + SM_AH, sbase + SM_BH, acc, mbase, nbase, lane);
  hpass(sbase + SM_AH, sbase + SM_BL, acc, mbase, nbase, lane);
  hpass(sbase + SM_AL, sbase + SM_BH, acc, mbase, nbase, lane);

  // final epilogue: f_new = lrelu(D2 + aterm[src] + bterm[dst]); +residual; scatter
  #pragma unroll
  for (int mt = 0; mt < 2; ++mt) {
    #pragma unroll
    for (int hr = 0; hr < 2; ++hr) {
      int row = mbase + mt*16 + qrow + hr*8;
      long e = row0 + row;
      int s = sSrc[row], d = sDst[row];
      #pragma unroll
      for (int nt = 0; nt < 8; ++nt) {
        int c = nbase + nt*8 + qcol*2;
        float2 a2 = *reinterpret_cast<const float2*>(d_aterm + (size_t)s*DD + c);
        float2 b2 = *reinterpret_cast<const float2*>(d_bterm + (size_t)d*DD + c);
        float f0 = lrelu(acc[mt][nt][hr*2]   + a2.x + b2.x);
        float f1 = lrelu(acc[mt][nt][hr*2+1] + a2.y + b2.y);
        float2 er = *reinterpret_cast<const float2*>(edge + (size_t)e*DD + c);
        *reinterpret_cast<float2*>(out_edge + (size_t)e*DD + c) = make_float2(f0+er.x, f1+er.y);
        red2(d_hfsum + (size_t)d*DD + c, f0, f1);
      }
    }
  }
}

// ---- kC: node update + pooling (SIMT) ----
__global__ __launch_bounds__(256) void kC(
    const float* __restrict__ node, const float* __restrict__ graph,
    const int* __restrict__ n2g, const float* __restrict__ Wnu,
    float* __restrict__ out_node)
{
  extern __shared__ float sm[];
  float* Hf = sm; float* Bs = sm + 64*DD;
  int*   sG = reinterpret_cast<int*>(sm + 80*DD);
  float* sD = sm + 80*DD + 64;
  int tid = threadIdx.x, tx = tid & 15, ty = tid >> 4;
  int row0 = blockIdx.x * 64, c0 = tx*4, cB = 64 + tx*4;

  for (int i = tid; i < 64*32; i += 256) {
    int n = row0 + (i >> 5), q = i & 31;
    float4 v = make_float4(0,0,0,0);
    if (n < NN) v = reinterpret_cast<const float4*>(d_hfsum)[(size_t)n*32 + q];
    reinterpret_cast<float4*>(Hf)[i] = v;
  }
  if (tid < 64) {
    int n = row0 + tid, g = 0, dg = 0;
    if (n < NN) { g = n2g[n]; dg = d_deg[n]; atomicAdd(&d_necnt[g], dg); }
    sG[tid] = g;
    sD[tid] = 1.f / fmaxf((float)dg, 1.f);
  }
  __syncthreads();

  #pragma unroll
  for (int i=0;i<4;i++){
    int r = ty*4+i, n = row0 + r; if (n >= NN) continue;
    int g = sG[r];
    float4 h0 = reinterpret_cast<float4*>(Hf)[r*32 + tx];
    float4 h1 = reinterpret_cast<float4*>(Hf)[r*32 + 16 + tx];
    red4(d_epool + g*DD + c0, h0);
    red4(d_epool + g*DD + cB, h1);
    float4 g0 = reinterpret_cast<const float4*>(graph)[(size_t)n*32 + tx];
    float4 g1 = reinterpret_cast<const float4*>(graph)[(size_t)n*32 + 16 + tx];
    red4(d_gpool + g*DD + c0, g0);
    red4(d_gpool + g*DD + cB, g1);
    float rd = sD[r];
    h0.x*=rd; h0.y*=rd; h0.z*=rd; h0.w*=rd;
    h1.x*=rd; h1.y*=rd; h1.z*=rd; h1.w*=rd;
    reinterpret_cast<float4*>(Hf)[r*32 + tx] = h0;
    reinterpret_cast<float4*>(Hf)[r*32 + 16 + tx] = h1;
  }

  u64 acc[4][4];
  ZACC4(acc); mm_pass(Hf, Wnu + 128*DD, acc, Bs, ty, tx, tid);

  #pragma unroll
  for (int i=0;i<4;i++){
    int r = ty*4+i, n = row0 + r; if (n >= NN) continue;
    float v[8]; unpack_acc(acc[i], v);
    const float* cr = d_c1 + (size_t)n*DD;
    float f0=lrelu(v[0]+cr[c0]),   f1=lrelu(v[1]+cr[c0+1]);
    float f2=lrelu(v[2]+cr[c0+2]), f3=lrelu(v[3]+cr[c0+3]);
    float f4=lrelu(v[4]+cr[cB]),   f5=lrelu(v[5]+cr[cB+1]);
    float f6=lrelu(v[6]+cr[cB+2]), f7=lrelu(v[7]+cr[cB+3]);
    float4 n0 = reinterpret_cast<const float4*>(node)[(size_t)n*32 + tx];
    float4 n1 = reinterpret_cast<const float4*>(node)[(size_t)n*32 + 16 + tx];
    *reinterpret_cast<float4*>(out_node + (size_t)n*DD + c0) = make_float4(f0+n0.x,f1+n0.y,f2+n0.z,f3+n0.w);
    *reinterpret_cast<float4*>(out_node + (size_t)n*DD + cB) = make_float4(f4+n1.x,f5+n1.y,f6+n1.z,f7+n1.w);
    int g = sG[r];
    red4(d_npool + g*DD + c0, make_float4(f0,f1,f2,f3));
    red4(d_npool + g*DD + cB, make_float4(f4,f5,f6,f7));
  }
}

__global__ void kD(const float* __restrict__ Wnu, const float* __restrict__ bnu){
  __shared__ float sp[3*DD];
  int g = blockIdx.x, j = threadIdx.x;
  float rn = 1.f / fmaxf((float)d_nncnt[g], 1.f);
  float re = 1.f / fmaxf((float)d_necnt[g], 1.f);
  sp[j]      = d_npool[g*DD+j]*rn;
  sp[DD+j]   = d_epool[g*DD+j]*re;
  sp[2*DD+j] = d_gpool[g*DD+j]*rn;
  __syncthreads();
  float a = bnu[j];
  #pragma unroll 4
  for (int k = 0; k < 3*DD; ++k) a = fmaf(sp[k], Wnu[k*DD+j], a);
  d_gnew[g*DD+j] = lrelu(a);
}

__global__ void kE(const float* __restrict__ graph, const int* __restrict__ n2g,
                   float* __restrict__ out_graph){
  int t = blockIdx.x*blockDim.x + threadIdx.x;
  if (t >= NN*32) return;
  int n = t >> 5, q = t & 31;
  int g = n2g[n];
  float4 gv = reinterpret_cast<const float4*>(d_gnew)[g*32 + q];
  float4 rv = reinterpret_cast<const float4*>(graph)[(size_t)n*32 + q];
  reinterpret_cast<float4*>(out_graph)[t] = make_float4(gv.x+rv.x, gv.y+rv.y, gv.z+rv.z, gv.w+rv.w);
}

extern "C" void kernel_launch(void* const* d_in, const int* in_sizes, int n_in,
                              void* d_out, int out_size) {
  const float* node  = (const float*)d_in[0];
  const float* edge  = (const float*)d_in[1];
  const float* graph = (const float*)d_in[2];
  const int*   src   = (const int*)d_in[3];
  const int*   dst   = (const int*)d_in[4];
  const int*   n2g   = (const int*)d_in[5];
  const float* Wn  = (const float*)d_in[6];
  const float* bn  = (const float*)d_in[7];
  const float* We  = (const float*)d_in[8];
  const float* be  = (const float*)d_in[9];
  const float* Wg  = (const float*)d_in[10];
  const float* bg  = (const float*)d_in[11];
  const float* Weu = (const float*)d_in[12];
  const float* beu = (const float*)d_in[13];
  const float* Wnu = (const float*)d_in[14];
  const float* bnu = (const float*)d_in[15];
  float* out_node  = (float*)d_out;
  float* out_edge  = out_node + (size_t)NN*DD;
  float* out_graph = out_edge + (size_t)EE*DD;

  const int SMA = (2*64*DD + 16*DD) * 4;
  const int SMC = (80*DD) * 4 + 64*4 + 64*4;
  cudaFuncSetAttribute(kA, cudaFuncAttributeMaxDynamicSharedMemorySize, SMA);
  cudaFuncSetAttribute(kB, cudaFuncAttributeMaxDynamicSharedMemorySize, SM_TOT);
  cudaFuncSetAttribute(kC, cudaFuncAttributeMaxDynamicSharedMemorySize, SMC);

  kInit<<<(NN*DD + 255)/256, 256>>>();
  kCounts<<<(EE + 255)/256, 256>>>(dst, n2g);
  kW<<<dim3(128, 2), 128>>>(We, Weu);
  kA<<<(NN + 63)/64, 256, SMA>>>(node, graph, Wn, bn, Wg, bg, Weu, beu, Wnu, bnu);
  kB<<<EE/128, 256, SM_TOT>>>(edge, src, dst, be, out_edge);
  kC<<<(NN + 63)/64, 256, SMC>>>(node, graph, n2g, Wnu, out_node);
  kD<<<BB, DD>>>(Wnu, bnu);
  kE<<<(NN*32 + 255)/256, 256>>>(graph, n2g, out_graph);
}